// round 1
// baseline (speedup 1.0000x reference)
#include <cuda_runtime.h>
#include <math.h>
#include <stdint.h>
#include <stddef.h>

#define FEAT    36
#define NNODES  24
#define NROUTES 48
#define CH      128
#define COUT    32
#define RH      128
#define BATCH   512
#define NSEQ    (BATCH * NROUTES)     /* 24576 */
#define G3      (3 * RH)              /* 384   */
#define NROWS   (NNODES * NSEQ)       /* 589824 */

/* scratch (no allocation allowed -> __device__ globals) */
__device__ float g_x32[(size_t)NROWS * COUT];   /* [t][n][32] node embeddings, 75.5 MB */
__device__ float g_last[(size_t)NSEQ * RH];     /* last GRU hidden per sequence, 12.6 MB */

/* ==================== K1: customer MLP 36->128(tanh)->32(tanh) ==================== */
#define K1_ROWS 32
#define XT_ST   36    /* row stride for transposed x tile (36*4 % 16 == 0 for float4) */
#define HT_ST   36    /* row stride for transposed h tile */

__global__ __launch_bounds__(256) void k_cust(
    const float* __restrict__ cust,           /* [NSEQ][NNODES*FEAT] */
    const float* __restrict__ w1, const float* __restrict__ b1,
    const float* __restrict__ w2, const float* __restrict__ b2)
{
    __shared__ float xT[FEAT * XT_ST];        /* [36][36] transposed inputs  */
    __shared__ float hT[CH * HT_ST];          /* [128][36] transposed hidden */
    const int tid = threadIdx.x;
    const long long row0 = (long long)blockIdx.x * K1_ROWS;   /* row = t*NSEQ + n */

    for (int e = tid; e < K1_ROWS * FEAT; e += 256) {
        int s = e / FEAT, f = e - s * FEAT;
        long long row = row0 + s;
        int t = (int)(row / NSEQ);
        int n = (int)(row - (long long)t * NSEQ);
        xT[f * XT_ST + s] = cust[(size_t)n * (NNODES * FEAT) + t * FEAT + f];
    }
    __syncthreads();

    /* phase 1: hT[j][s] = tanh(b1[j] + sum_i xT[i][s] * w1[i][j]) */
    {
        const int j  = tid & 127;
        const int s0 = (tid >> 7) * 16;       /* two halves of 16 rows */
        float bb = b1[j];
        float4 a[4];
        #pragma unroll
        for (int u = 0; u < 4; u++) a[u] = make_float4(bb, bb, bb, bb);
        #pragma unroll
        for (int i = 0; i < FEAT; i++) {
            float w = w1[i * CH + j];
            const float4* xp = (const float4*)(xT + i * XT_ST + s0);
            #pragma unroll
            for (int u = 0; u < 4; u++) {
                float4 x = xp[u];
                a[u].x += w * x.x; a[u].y += w * x.y;
                a[u].z += w * x.z; a[u].w += w * x.w;
            }
        }
        float4* hp = (float4*)(hT + j * HT_ST + s0);
        #pragma unroll
        for (int u = 0; u < 4; u++) {
            float4 o;
            o.x = tanhf(a[u].x); o.y = tanhf(a[u].y);
            o.z = tanhf(a[u].z); o.w = tanhf(a[u].w);
            hp[u] = o;
        }
    }
    __syncthreads();

    /* phase 2: out[s][j2] = tanh(b2[j2] + sum_k hT[k][s] * w2[k][j2]) */
    {
        const int j2 = tid & 31;
        const int s0 = (tid >> 5) * 4;        /* 8 groups of 4 rows */
        float bb = b2[j2];
        float4 a = make_float4(bb, bb, bb, bb);
        #pragma unroll 8
        for (int k = 0; k < CH; k++) {
            float w = w2[k * COUT + j2];
            float4 h = *(const float4*)(hT + k * HT_ST + s0);
            a.x += w * h.x; a.y += w * h.y; a.z += w * h.z; a.w += w * h.w;
        }
        size_t base = (size_t)(row0 + s0) * COUT + j2;
        g_x32[base]            = tanhf(a.x);
        g_x32[base + COUT]     = tanhf(a.y);
        g_x32[base + 2 * COUT] = tanhf(a.z);
        g_x32[base + 3 * COUT] = tanhf(a.w);
    }
}

/* ==================== K2: fused 2-layer GRU over 24 steps ==================== */
#define STILE 64          /* sequences per block */
#define PAD   66          /* shared row stride (even -> float2 aligned; 2-way write conflicts only) */
#define GPT   2           /* seq-groups (of 8) per thread */
#define K2_SMEM ((2 * 128 * PAD + 32 * PAD) * 4)   /* 76032 bytes */

__device__ __forceinline__ float sigm(float x) { return 1.f / (1.f + expf(-x)); }

template <int IN>
__device__ __forceinline__ void gru_cell(
    const float* __restrict__ wih, const float* __restrict__ whh,
    float br, float bz, float bi, float bh,
    const float* xbuf,   /* shared [IN][PAD]  (transposed: [feature][seq]) */
    const float* hbuf,   /* shared [128][PAD] */
    int j, int sg, float2* hn)
{
    #pragma unroll
    for (int g = 0; g < GPT; g++) {
        const int s0 = (g * 4 + sg) * 8;
        float2 ar[4], az[4], ai[4], ah[4];
        #pragma unroll
        for (int u = 0; u < 4; u++) {
            ar[u] = make_float2(br, br); az[u] = make_float2(bz, bz);
            ai[u] = make_float2(bi, bi); ah[u] = make_float2(bh, bh);
        }
        /* input-to-hidden gates */
        #pragma unroll 4
        for (int i = 0; i < IN; i++) {
            float wr = wih[i * G3 + j];
            float wz = wih[i * G3 + 128 + j];
            float wn = wih[i * G3 + 256 + j];
            const float2* xp = (const float2*)(xbuf + i * PAD + s0);
            #pragma unroll
            for (int u = 0; u < 4; u++) {
                float2 x = xp[u];
                ar[u].x += wr * x.x; ar[u].y += wr * x.y;
                az[u].x += wz * x.x; az[u].y += wz * x.y;
                ai[u].x += wn * x.x; ai[u].y += wn * x.y;
            }
        }
        /* hidden-to-hidden gates */
        #pragma unroll 4
        for (int k = 0; k < RH; k++) {
            float wr = whh[k * G3 + j];
            float wz = whh[k * G3 + 128 + j];
            float wn = whh[k * G3 + 256 + j];
            const float2* hp = (const float2*)(hbuf + k * PAD + s0);
            #pragma unroll
            for (int u = 0; u < 4; u++) {
                float2 h = hp[u];
                ar[u].x += wr * h.x; ar[u].y += wr * h.y;
                az[u].x += wz * h.x; az[u].y += wz * h.y;
                ah[u].x += wn * h.x; ah[u].y += wn * h.y;
            }
        }
        /* gate nonlinearities + state update (r,z,n order as in reference) */
        #pragma unroll
        for (int u = 0; u < 4; u++) {
            float2 hold = *(const float2*)(hbuf + j * PAD + s0 + 2 * u);
            float2 o;
            {
                float r = sigm(ar[u].x), z = sigm(az[u].x);
                float n = tanhf(ai[u].x + r * ah[u].x);
                o.x = (1.f - z) * n + z * hold.x;
            }
            {
                float r = sigm(ar[u].y), z = sigm(az[u].y);
                float n = tanhf(ai[u].y + r * ah[u].y);
                o.y = (1.f - z) * n + z * hold.y;
            }
            hn[g * 4 + u] = o;
        }
    }
}

__global__ __launch_bounds__(512, 1) void k_gru(
    const float* __restrict__ wih0, const float* __restrict__ whh0,
    const float* __restrict__ bih0, const float* __restrict__ bhh0,
    const float* __restrict__ wih1, const float* __restrict__ whh1,
    const float* __restrict__ bih1, const float* __restrict__ bhh1)
{
    extern __shared__ float smem[];
    float* h0buf = smem;                   /* [128][PAD] layer-0 state / layer-1 input */
    float* h1buf = smem + 128 * PAD;       /* [128][PAD] layer-1 state */
    float* xt    = smem + 2 * 128 * PAD;   /* [32][PAD]  step input (transposed) */
    const int tid = threadIdx.x;
    const int j   = tid & 127;
    const int sg  = tid >> 7;              /* 0..3 */
    const int nbase = blockIdx.x * STILE;

    for (int i = tid; i < 2 * 128 * PAD; i += 512) smem[i] = 0.f;  /* h0 = h1 = 0 */

    const float br0 = bih0[j] + bhh0[j];
    const float bz0 = bih0[128 + j] + bhh0[128 + j];
    const float bi0 = bih0[256 + j];
    const float bh0 = bhh0[256 + j];
    const float br1 = bih1[j] + bhh1[j];
    const float bz1 = bih1[128 + j] + bhh1[128 + j];
    const float bi1 = bih1[256 + j];
    const float bh1 = bhh1[256 + j];

    float2 hn[GPT * 4];

    for (int t = 0; t < NNODES; t++) {
        /* load & transpose this step's inputs: 64 seqs x 32 feats */
        const float* src = g_x32 + ((size_t)t * NSEQ + nbase) * COUT;
        #pragma unroll
        for (int rep = 0; rep < 4; rep++) {
            int e = tid + rep * 512;
            xt[(e & 31) * PAD + (e >> 5)] = src[e];
        }
        __syncthreads();   /* also orders zero-init on t==0 */

        gru_cell<COUT>(wih0, whh0, br0, bz0, bi0, bh0, xt, h0buf, j, sg, hn);
        __syncthreads();
        #pragma unroll
        for (int g = 0; g < GPT; g++) {
            int s0 = (g * 4 + sg) * 8;
            #pragma unroll
            for (int u = 0; u < 4; u++)
                *(float2*)(h0buf + j * PAD + s0 + 2 * u) = hn[g * 4 + u];
        }
        __syncthreads();

        gru_cell<RH>(wih1, whh1, br1, bz1, bi1, bh1, h0buf, h1buf, j, sg, hn);
        __syncthreads();
        #pragma unroll
        for (int g = 0; g < GPT; g++) {
            int s0 = (g * 4 + sg) * 8;
            #pragma unroll
            for (int u = 0; u < 4; u++)
                *(float2*)(h1buf + j * PAD + s0 + 2 * u) = hn[g * 4 + u];
        }
        __syncthreads();
    }

    /* hn still holds the final (t = 23) layer-1 state for this thread's cells */
    #pragma unroll
    for (int g = 0; g < GPT; g++) {
        int s0 = (g * 4 + sg) * 8;
        #pragma unroll
        for (int u = 0; u < 4; u++) {
            int s = s0 + 2 * u;
            g_last[(size_t)(nbase + s) * RH + j]     = hn[g * 4 + u].x;
            g_last[(size_t)(nbase + s + 1) * RH + j] = hn[g * 4 + u].y;
        }
    }
}

/* ==================== K3: mean over routes + head MLP ==================== */
__global__ __launch_bounds__(128) void k_final(
    const float* __restrict__ cand,
    const float* __restrict__ cand_w, const float* __restrict__ cand_b,
    const float* __restrict__ fc1w, const float* __restrict__ fc1b,
    const float* __restrict__ fc2w, const float* __restrict__ fc2b,
    const float* __restrict__ fc3w, const float* __restrict__ fc3b,
    float* __restrict__ out)
{
    __shared__ float xr[RH + 64];   /* concat [x_r(128), x_c(64)] */
    __shared__ float h[128];
    __shared__ float red[128];
    const int b = blockIdx.x, tid = threadIdx.x;

    /* x_r: mean over 48 routes of last hidden */
    {
        const float* base = g_last + (size_t)b * NROUTES * RH;
        float acc = 0.f;
        #pragma unroll 8
        for (int r = 0; r < NROUTES; r++) acc += base[r * RH + tid];
        xr[tid] = acc * (1.f / NROUTES);
    }
    /* x_c = candidates @ cand_w + cand_b (no activation) */
    if (tid < 64) {
        float a = cand_b[tid];
        #pragma unroll 8
        for (int i = 0; i < 2 * FEAT; i++)
            a += cand[b * 2 * FEAT + i] * cand_w[i * 64 + tid];
        xr[RH + tid] = a;
    }
    __syncthreads();

    {
        float a = fc1b[tid];
        #pragma unroll 8
        for (int i = 0; i < RH + 64; i++) a += xr[i] * fc1w[i * 128 + tid];
        h[tid] = tanhf(a);
    }
    __syncthreads();
    {
        float a = fc2b[tid];
        #pragma unroll 8
        for (int i = 0; i < 128; i++) a += h[i] * fc2w[i * 128 + tid];
        red[tid] = tanhf(a) * fc3w[tid];
    }
    __syncthreads();
    for (int s = 64; s > 0; s >>= 1) {
        if (tid < s) red[tid] += red[tid + s];
        __syncthreads();
    }
    if (tid == 0) out[b] = red[0] + fc3b[0];
}

/* ==================== launch ==================== */
extern "C" void kernel_launch(void* const* d_in, const int* in_sizes, int n_in,
                              void* d_out, int out_size)
{
    const float* candidates = (const float*)d_in[0];
    const float* customers  = (const float*)d_in[1];
    const float* cust_w1 = (const float*)d_in[2];
    const float* cust_b1 = (const float*)d_in[3];
    const float* cust_w2 = (const float*)d_in[4];
    const float* cust_b2 = (const float*)d_in[5];
    const float* wih0 = (const float*)d_in[6];
    const float* whh0 = (const float*)d_in[7];
    const float* bih0 = (const float*)d_in[8];
    const float* bhh0 = (const float*)d_in[9];
    const float* wih1 = (const float*)d_in[10];
    const float* whh1 = (const float*)d_in[11];
    const float* bih1 = (const float*)d_in[12];
    const float* bhh1 = (const float*)d_in[13];
    const float* cand_w = (const float*)d_in[14];
    const float* cand_b = (const float*)d_in[15];
    const float* fc1w = (const float*)d_in[16];
    const float* fc1b = (const float*)d_in[17];
    const float* fc2w = (const float*)d_in[18];
    const float* fc2b = (const float*)d_in[19];
    const float* fc3w = (const float*)d_in[20];
    const float* fc3b = (const float*)d_in[21];

    cudaFuncSetAttribute(k_gru, cudaFuncAttributeMaxDynamicSharedMemorySize, K2_SMEM);

    k_cust<<<NROWS / K1_ROWS, 256>>>(customers, cust_w1, cust_b1, cust_w2, cust_b2);
    k_gru<<<NSEQ / STILE, 512, K2_SMEM>>>(wih0, whh0, bih0, bhh0,
                                          wih1, whh1, bih1, bhh1);
    k_final<<<BATCH, 128>>>(candidates, cand_w, cand_b,
                            fc1w, fc1b, fc2w, fc2b, fc3w, fc3b,
                            (float*)d_out);
}

// round 2
// speedup vs baseline: 1.3016x; 1.3016x over previous
#include <cuda_runtime.h>
#include <math.h>
#include <stdint.h>
#include <stddef.h>

#define FEAT    36
#define NNODES  24
#define NROUTES 48
#define CH      128
#define COUT    32
#define RH      128
#define BATCH   512
#define NSEQ    (BATCH * NROUTES)     /* 24576 */
#define G3      (3 * RH)              /* 384   */
#define NROWS   (NNODES * NSEQ)       /* 589824 */

typedef unsigned long long ull;

/* ---- packed f32x2 helpers (SASS FFMA2 path, only reachable via PTX) ---- */
__device__ __forceinline__ ull pack2s(float x) {
    ull r; asm("mov.b64 %0, {%1, %1};" : "=l"(r) : "f"(x)); return r;
}
__device__ __forceinline__ ull pack2(float x, float y) {
    ull r; asm("mov.b64 %0, {%1, %2};" : "=l"(r) : "f"(x), "f"(y)); return r;
}
__device__ __forceinline__ ull ffma2(ull a, ull b, ull c) {
    ull d; asm("fma.rn.f32x2 %0, %1, %2, %3;" : "=l"(d) : "l"(a), "l"(b), "l"(c)); return d;
}
__device__ __forceinline__ float2 unpk(ull v) {
    float lo, hi; asm("mov.b64 {%0, %1}, %2;" : "=f"(lo), "=f"(hi) : "l"(v));
    return make_float2(lo, hi);
}
__device__ __forceinline__ float sigm(float x) { return 1.f / (1.f + expf(-x)); }

/* scratch (no allocation allowed -> __device__ globals) */
__device__ float g_x32[(size_t)NROWS * COUT];   /* [t][n][32] node embeddings */
__device__ float g_last[(size_t)NSEQ * RH];     /* last GRU hidden per sequence */

/* ==================== K1: customer MLP 36->128(tanh)->32(tanh) ==================== */
#define K1_ROWS 64
#define XT_ST   68
#define HT_ST   68

__global__ __launch_bounds__(256) void k_cust(
    const float* __restrict__ cust,           /* [NSEQ][NNODES*FEAT] */
    const float* __restrict__ w1, const float* __restrict__ b1,
    const float* __restrict__ w2, const float* __restrict__ b2)
{
    __shared__ __align__(16) float xT[FEAT * XT_ST];   /* [36][68] transposed inputs  */
    __shared__ __align__(16) float hT[CH * HT_ST];     /* [128][68] transposed hidden */
    const int tid = threadIdx.x;
    const long long row0 = (long long)blockIdx.x * K1_ROWS;   /* row = t*NSEQ + n */

    #pragma unroll
    for (int rep = 0; rep < K1_ROWS * FEAT / 256; rep++) {
        int e = tid + rep * 256;
        int s = e / FEAT, f = e - s * FEAT;
        long long row = row0 + s;
        int t = (int)(row / NSEQ);
        int n = (int)(row - (long long)t * NSEQ);
        xT[f * XT_ST + s] = cust[(size_t)n * (NNODES * FEAT) + t * FEAT + f];
    }
    __syncthreads();

    /* phase 1: hT[j][s] = tanh(b1[j] + sum_i xT[i][s] * w1[i][j]) */
    {
        const int j  = tid & 127;
        const int s0 = (tid >> 7) * 32;       /* two halves of 32 rows */
        ull a[16];
        ull bb = pack2s(b1[j]);
        #pragma unroll
        for (int u = 0; u < 16; u++) a[u] = bb;
        #pragma unroll 4
        for (int i = 0; i < FEAT; i++) {
            ull w = pack2s(w1[i * CH + j]);
            const ulonglong2* xp = (const ulonglong2*)(xT + i * XT_ST + s0);
            #pragma unroll
            for (int q = 0; q < 8; q++) {
                ulonglong2 v = xp[q];
                a[2 * q]     = ffma2(w, v.x, a[2 * q]);
                a[2 * q + 1] = ffma2(w, v.y, a[2 * q + 1]);
            }
        }
        float* hp = hT + j * HT_ST + s0;
        #pragma unroll
        for (int q = 0; q < 8; q++) {
            float2 p0 = unpk(a[2 * q]), p1 = unpk(a[2 * q + 1]);
            float4 o = make_float4(tanhf(p0.x), tanhf(p0.y), tanhf(p1.x), tanhf(p1.y));
            *(float4*)(hp + 4 * q) = o;
        }
    }
    __syncthreads();

    /* phase 2: out[s][j2] = tanh(b2[j2] + sum_k hT[k][s] * w2[k][j2]) */
    {
        const int j2 = tid & 31;
        const int s0 = (tid >> 5) * 8;        /* 8 groups of 8 rows */
        ull a[4];
        ull bb = pack2s(b2[j2]);
        #pragma unroll
        for (int u = 0; u < 4; u++) a[u] = bb;
        #pragma unroll 4
        for (int k = 0; k < CH; k++) {
            ull w = pack2s(w2[k * COUT + j2]);
            const ulonglong2* hp = (const ulonglong2*)(hT + k * HT_ST + s0);
            ulonglong2 v0 = hp[0], v1 = hp[1];
            a[0] = ffma2(w, v0.x, a[0]);
            a[1] = ffma2(w, v0.y, a[1]);
            a[2] = ffma2(w, v1.x, a[2]);
            a[3] = ffma2(w, v1.y, a[3]);
        }
        size_t base = (size_t)(row0 + s0) * COUT + j2;
        #pragma unroll
        for (int q = 0; q < 4; q++) {
            float2 p = unpk(a[q]);
            g_x32[base + (size_t)(2 * q) * COUT]     = tanhf(p.x);
            g_x32[base + (size_t)(2 * q + 1) * COUT] = tanhf(p.y);
        }
    }
}

/* ==================== K2: fused 2-layer GRU over 24 steps ==================== */
#define STILE 64          /* sequences per block */
#define PAD   66          /* shared row stride (8B aligned pairs; 2-way write conflicts only) */
#define K2_SMEM ((2 * 128 * PAD + 32 * PAD) * 4)   /* 76032 bytes */

/* One GRU cell step for 16 sequences (2 blocks of 8) handled by this thread.
   All inner-loop shared reads are warp-broadcast (all lanes same address). */
template <int IN>
__device__ __forceinline__ void gru_cell(
    const float* __restrict__ wih, const float* __restrict__ whh,
    const float* __restrict__ bih, const float* __restrict__ bhh,
    const float* xbuf,   /* shared [IN][PAD]  (transposed: [feature][seq]) */
    const float* hbuf,   /* shared [128][PAD] */
    int j, int sA, ull* hn)
{
    ull ar[8], az[8], ai[8], ah[8];
    {
        ull br2 = pack2s(bih[j] + bhh[j]);
        ull bz2 = pack2s(bih[128 + j] + bhh[128 + j]);
        ull bi2 = pack2s(bih[256 + j]);
        ull bh2 = pack2s(bhh[256 + j]);
        #pragma unroll
        for (int u = 0; u < 8; u++) { ar[u] = br2; az[u] = bz2; ai[u] = bi2; ah[u] = bh2; }
    }

    /* input-to-hidden gates */
    #pragma unroll 4
    for (int i = 0; i < IN; i++) {
        const float* wp = wih + i * G3 + j;
        ull wr2 = pack2s(wp[0]);
        ull wz2 = pack2s(wp[128]);
        ull wn2 = pack2s(wp[256]);
        const ull* xa = (const ull*)(xbuf + i * PAD + sA);
        #pragma unroll
        for (int u = 0; u < 4; u++) {
            ull x = xa[u];
            ar[u] = ffma2(wr2, x, ar[u]);
            az[u] = ffma2(wz2, x, az[u]);
            ai[u] = ffma2(wn2, x, ai[u]);
        }
        const ull* xb = (const ull*)(xbuf + i * PAD + sA + 32);
        #pragma unroll
        for (int u = 0; u < 4; u++) {
            ull x = xb[u];
            ar[4 + u] = ffma2(wr2, x, ar[4 + u]);
            az[4 + u] = ffma2(wz2, x, az[4 + u]);
            ai[4 + u] = ffma2(wn2, x, ai[4 + u]);
        }
    }
    /* hidden-to-hidden gates */
    #pragma unroll 4
    for (int k = 0; k < RH; k++) {
        const float* wp = whh + k * G3 + j;
        ull wr2 = pack2s(wp[0]);
        ull wz2 = pack2s(wp[128]);
        ull wn2 = pack2s(wp[256]);
        const ull* ha = (const ull*)(hbuf + k * PAD + sA);
        #pragma unroll
        for (int u = 0; u < 4; u++) {
            ull h = ha[u];
            ar[u] = ffma2(wr2, h, ar[u]);
            az[u] = ffma2(wz2, h, az[u]);
            ah[u] = ffma2(wn2, h, ah[u]);
        }
        const ull* hb = (const ull*)(hbuf + k * PAD + sA + 32);
        #pragma unroll
        for (int u = 0; u < 4; u++) {
            ull h = hb[u];
            ar[4 + u] = ffma2(wr2, h, ar[4 + u]);
            az[4 + u] = ffma2(wz2, h, az[4 + u]);
            ah[4 + u] = ffma2(wn2, h, ah[4 + u]);
        }
    }
    /* gate nonlinearities + state update (r,z,n order as in reference) */
    #pragma unroll
    for (int u = 0; u < 8; u++) {
        int s = sA + ((u < 4) ? 2 * u : 32 + 2 * (u - 4));
        float2 hold = *(const float2*)(hbuf + j * PAD + s);
        float2 R = unpk(ar[u]), Z = unpk(az[u]), I = unpk(ai[u]), H = unpk(ah[u]);
        float r0 = sigm(R.x), z0 = sigm(Z.x);
        float n0 = tanhf(I.x + r0 * H.x);
        float o0 = (1.f - z0) * n0 + z0 * hold.x;
        float r1 = sigm(R.y), z1 = sigm(Z.y);
        float n1 = tanhf(I.y + r1 * H.y);
        float o1 = (1.f - z1) * n1 + z1 * hold.y;
        hn[u] = pack2(o0, o1);
    }
}

__global__ __launch_bounds__(512, 1) void k_gru(
    const float* __restrict__ wih0, const float* __restrict__ whh0,
    const float* __restrict__ bih0, const float* __restrict__ bhh0,
    const float* __restrict__ wih1, const float* __restrict__ whh1,
    const float* __restrict__ bih1, const float* __restrict__ bhh1)
{
    extern __shared__ float smem[];
    float* h0buf = smem;                   /* [128][PAD] layer-0 state / layer-1 input */
    float* h1buf = smem + 128 * PAD;       /* [128][PAD] layer-1 state */
    float* xt    = smem + 2 * 128 * PAD;   /* [32][PAD]  step input (transposed) */
    const int tid = threadIdx.x;
    const int j   = tid & 127;
    const int sA  = (tid >> 7) * 8;        /* first 8-seq block; second is +32 */
    const int nbase = blockIdx.x * STILE;

    for (int i = tid; i < 2 * 128 * PAD; i += 512) smem[i] = 0.f;  /* h0 = h1 = 0 */

    ull hn[8];

    for (int t = 0; t < NNODES; t++) {
        /* load & transpose this step's inputs: 64 seqs x 32 feats */
        const float* src = g_x32 + ((size_t)t * NSEQ + nbase) * COUT;
        #pragma unroll
        for (int rep = 0; rep < 4; rep++) {
            int e = tid + rep * 512;
            xt[(e & 31) * PAD + (e >> 5)] = src[e];
        }
        __syncthreads();   /* also orders zero-init on t==0 and h1 stores of t-1 */

        gru_cell<COUT>(wih0, whh0, bih0, bhh0, xt, h0buf, j, sA, hn);
        __syncthreads();
        #pragma unroll
        for (int u = 0; u < 8; u++) {
            int s = sA + ((u < 4) ? 2 * u : 32 + 2 * (u - 4));
            *(ull*)(h0buf + j * PAD + s) = hn[u];
        }
        __syncthreads();

        gru_cell<RH>(wih1, whh1, bih1, bhh1, h0buf, h1buf, j, sA, hn);
        __syncthreads();
        #pragma unroll
        for (int u = 0; u < 8; u++) {
            int s = sA + ((u < 4) ? 2 * u : 32 + 2 * (u - 4));
            *(ull*)(h1buf + j * PAD + s) = hn[u];
        }
    }

    /* hn holds the final (t = 23) layer-1 state for this thread's cells */
    #pragma unroll
    for (int u = 0; u < 8; u++) {
        int s = sA + ((u < 4) ? 2 * u : 32 + 2 * (u - 4));
        float2 v = unpk(hn[u]);
        g_last[(size_t)(nbase + s) * RH + j]     = v.x;
        g_last[(size_t)(nbase + s + 1) * RH + j] = v.y;
    }
}

/* ==================== K3: mean over routes + head MLP ==================== */
__global__ __launch_bounds__(128) void k_final(
    const float* __restrict__ cand,
    const float* __restrict__ cand_w, const float* __restrict__ cand_b,
    const float* __restrict__ fc1w, const float* __restrict__ fc1b,
    const float* __restrict__ fc2w, const float* __restrict__ fc2b,
    const float* __restrict__ fc3w, const float* __restrict__ fc3b,
    float* __restrict__ out)
{
    __shared__ float xr[RH + 64];   /* concat [x_r(128), x_c(64)] */
    __shared__ float h[128];
    __shared__ float red[128];
    const int b = blockIdx.x, tid = threadIdx.x;

    /* x_r: mean over 48 routes of last hidden */
    {
        const float* base = g_last + (size_t)b * NROUTES * RH;
        float acc = 0.f;
        #pragma unroll 8
        for (int r = 0; r < NROUTES; r++) acc += base[r * RH + tid];
        xr[tid] = acc * (1.f / NROUTES);
    }
    /* x_c = candidates @ cand_w + cand_b (no activation) */
    if (tid < 64) {
        float a = cand_b[tid];
        #pragma unroll 8
        for (int i = 0; i < 2 * FEAT; i++)
            a += cand[b * 2 * FEAT + i] * cand_w[i * 64 + tid];
        xr[RH + tid] = a;
    }
    __syncthreads();

    {
        float a = fc1b[tid];
        #pragma unroll 8
        for (int i = 0; i < RH + 64; i++) a += xr[i] * fc1w[i * 128 + tid];
        h[tid] = tanhf(a);
    }
    __syncthreads();
    {
        float a = fc2b[tid];
        #pragma unroll 8
        for (int i = 0; i < 128; i++) a += h[i] * fc2w[i * 128 + tid];
        red[tid] = tanhf(a) * fc3w[tid];
    }
    __syncthreads();
    for (int s = 64; s > 0; s >>= 1) {
        if (tid < s) red[tid] += red[tid + s];
        __syncthreads();
    }
    if (tid == 0) out[b] = red[0] + fc3b[0];
}

/* ==================== launch ==================== */
extern "C" void kernel_launch(void* const* d_in, const int* in_sizes, int n_in,
                              void* d_out, int out_size)
{
    const float* candidates = (const float*)d_in[0];
    const float* customers  = (const float*)d_in[1];
    const float* cust_w1 = (const float*)d_in[2];
    const float* cust_b1 = (const float*)d_in[3];
    const float* cust_w2 = (const float*)d_in[4];
    const float* cust_b2 = (const float*)d_in[5];
    const float* wih0 = (const float*)d_in[6];
    const float* whh0 = (const float*)d_in[7];
    const float* bih0 = (const float*)d_in[8];
    const float* bhh0 = (const float*)d_in[9];
    const float* wih1 = (const float*)d_in[10];
    const float* whh1 = (const float*)d_in[11];
    const float* bih1 = (const float*)d_in[12];
    const float* bhh1 = (const float*)d_in[13];
    const float* cand_w = (const float*)d_in[14];
    const float* cand_b = (const float*)d_in[15];
    const float* fc1w = (const float*)d_in[16];
    const float* fc1b = (const float*)d_in[17];
    const float* fc2w = (const float*)d_in[18];
    const float* fc2b = (const float*)d_in[19];
    const float* fc3w = (const float*)d_in[20];
    const float* fc3b = (const float*)d_in[21];

    cudaFuncSetAttribute(k_gru, cudaFuncAttributeMaxDynamicSharedMemorySize, K2_SMEM);

    k_cust<<<NROWS / K1_ROWS, 256>>>(customers, cust_w1, cust_b1, cust_w2, cust_b2);
    k_gru<<<NSEQ / STILE, 512, K2_SMEM>>>(wih0, whh0, bih0, bhh0,
                                          wih1, whh1, bih1, bhh1);
    k_final<<<BATCH, 128>>>(candidates, cand_w, cand_b,
                            fc1w, fc1b, fc2w, fc2b, fc3w, fc3b,
                            (float*)d_out);
}